// round 16
// baseline (speedup 1.0000x reference)
#include <cuda_runtime.h>
#include <cuda_fp16.h>

#define NB 2
#define NS 2048
#define ND 1024
#define NH 16
#define HD 64
#define NM (NB * NS)

// fp16 intermediates
__device__ __half g_q[NB * NH * NS * HD];
__device__ __half g_k[NB * NH * NS * HD];
__device__ __half g_v[NB * NH * NS * HD];
__device__ __half g_xh[3 * NM * ND];   // X fp16
__device__ __half g_wt[3 * ND * ND];   // W transposed [n][k] fp16

// ---------------------------------------------------------------------------
// primitives
// ---------------------------------------------------------------------------
static __device__ __forceinline__ void mma_f16(float* d, const unsigned* a,
                                               const unsigned* b) {
    asm volatile(
        "mma.sync.aligned.m16n8k16.row.col.f32.f16.f16.f32 "
        "{%0,%1,%2,%3}, {%4,%5,%6,%7}, {%8,%9}, {%0,%1,%2,%3};"
        : "+f"(d[0]), "+f"(d[1]), "+f"(d[2]), "+f"(d[3])
        : "r"(a[0]), "r"(a[1]), "r"(a[2]), "r"(a[3]), "r"(b[0]), "r"(b[1]));
}
static __device__ __forceinline__ void mma_f16h(unsigned* d, const unsigned* a,
                                                const unsigned* b) {
    asm volatile(
        "mma.sync.aligned.m16n8k16.row.col.f16.f16.f16.f16 "
        "{%0,%1}, {%2,%3,%4,%5}, {%6,%7}, {%0,%1};"
        : "+r"(d[0]), "+r"(d[1])
        : "r"(a[0]), "r"(a[1]), "r"(a[2]), "r"(a[3]), "r"(b[0]), "r"(b[1]));
}
static __device__ __forceinline__ void ldsm4(unsigned* r, const unsigned* p) {
    unsigned a = (unsigned)__cvta_generic_to_shared(p);
    asm volatile("ldmatrix.sync.aligned.m8n8.x4.shared.b16 {%0,%1,%2,%3}, [%4];"
                 : "=r"(r[0]), "=r"(r[1]), "=r"(r[2]), "=r"(r[3]) : "r"(a));
}
static __device__ __forceinline__ void ldsm4t(unsigned* r, const unsigned* p) {
    unsigned a = (unsigned)__cvta_generic_to_shared(p);
    asm volatile("ldmatrix.sync.aligned.m8n8.x4.trans.shared.b16 {%0,%1,%2,%3}, [%4];"
                 : "=r"(r[0]), "=r"(r[1]), "=r"(r[2]), "=r"(r[3]) : "r"(a));
}
static __device__ __forceinline__ void cpa16(const unsigned* smdst, const void* gsrc) {
    unsigned a = (unsigned)__cvta_generic_to_shared(smdst);
    asm volatile("cp.async.cg.shared.global [%0], [%1], 16;" :: "r"(a), "l"(gsrc));
}
#define CPA_COMMIT() asm volatile("cp.async.commit_group;" ::: "memory")
#define CPA_WAIT(n)  asm volatile("cp.async.wait_group %0;" :: "n"(n) : "memory")

static __device__ __forceinline__ unsigned pack2h(float x, float y) {
    __half2 h = __floats2half2_rn(x, y);
    return *(unsigned*)&h;
}
static __device__ __forceinline__ unsigned hex2(unsigned x) {
    unsigned y;
    asm("ex2.approx.f16x2 %0, %1;" : "=r"(y) : "r"(x));
    return y;
}
static __device__ __forceinline__ __half2 u2h2(unsigned x) {
    return *(__half2*)&x;
}

// fragment lane->word offsets (row stride S words)
#define AOFFS(lane, S) \
    ((((lane) & 7) + ((((lane) >> 3) & 1) << 3)) * (S) + ((((lane) >> 4) & 1) << 2))
#define BOFFS(lane, S) \
    ((((lane) & 7) + ((((lane) >> 4) & 1) << 3)) * (S) + ((((lane) >> 3) & 1) << 2))

// ---------------------------------------------------------------------------
// Convert X -> fp16
// ---------------------------------------------------------------------------
__global__ void convx_kernel(const float* __restrict__ xq,
                             const float* __restrict__ xk,
                             const float* __restrict__ xv) {
    const int z = blockIdx.y;
    const float* X = (z == 0) ? xq : (z == 1) ? xk : xv;
    unsigned* xh = (unsigned*)(g_xh + (size_t)z * NM * ND);
    int i = blockIdx.x * blockDim.x + threadIdx.x;
    float4 v = ((const float4*)X)[i];
    xh[2 * i]     = pack2h(v.x, v.y);
    xh[2 * i + 1] = pack2h(v.z, v.w);
}

// ---------------------------------------------------------------------------
// Convert + transpose W -> Wt[n][k] fp16
// ---------------------------------------------------------------------------
__global__ void convw_kernel(const float* __restrict__ wq,
                             const float* __restrict__ wk,
                             const float* __restrict__ wv) {
    __shared__ float t[32][33];
    const int z = blockIdx.z;
    const float* W = (z == 0) ? wq : (z == 1) ? wk : wv;
    __half* Wt = g_wt + (size_t)z * ND * ND;
    const int k0 = blockIdx.y * 32, n0 = blockIdx.x * 32;
    const int tx = threadIdx.x, ty = threadIdx.y;   // 32 x 8
#pragma unroll
    for (int j = 0; j < 4; j++)
        t[ty * 4 + j][tx] = W[(size_t)(k0 + ty * 4 + j) * ND + n0 + tx];
    __syncthreads();
    unsigned* dst = (unsigned*)Wt;
#pragma unroll
    for (int j = 0; j < 4; j++) {
        int n = ty * 4 + j;
        if (tx < 16) {
            float a = t[tx * 2][n], b = t[tx * 2 + 1][n];
            dst[((size_t)(n0 + n) * ND + k0) / 2 + tx] = pack2h(a, b);
        }
    }
}

// ---------------------------------------------------------------------------
// Projection GEMM (unchanged): single-term fp16, BK=64, 2-stage (1 in flight).
// ---------------------------------------------------------------------------
#define PS 36
#define PBUF (2 * 128 * PS)
#define PXH_ 0
#define PWT_ (128 * PS)
#define PROJ_SMEM (2 * PBUF * 4)          // 73728 B

__global__ __launch_bounds__(256, 2)
void proj_kernel(const float* __restrict__ bq, const float* __restrict__ bk,
                 const float* __restrict__ bv) {
    extern __shared__ unsigned sm[];
    const int z = blockIdx.z;
    const float* bias = (z == 0) ? bq : (z == 1) ? bk : bv;
    __half* dst = (z == 0) ? g_q : (z == 1) ? g_k : g_v;
    const float sc = (z == 0) ? 0.125f : (z == 1) ? 1.4426950408889634f : 1.0f;
    const __half* Xh = g_xh + (size_t)z * NM * ND;
    const __half* Wt = g_wt + (size_t)z * ND * ND;

    const int tid = threadIdx.x;
    const int lane = tid & 31, wid = tid >> 5;
    const int warp_m = (wid >> 2) * 64, warp_n = (wid & 3) * 32;
    const int m0 = blockIdx.y * 128, n0 = blockIdx.x * 128;
    const int g4 = lane >> 2, l4 = lane & 3;
    const int aoff = AOFFS(lane, PS), boff = BOFFS(lane, PS);

    float acc[4][4][4];
#pragma unroll
    for (int mf = 0; mf < 4; mf++)
#pragma unroll
        for (int nf = 0; nf < 4; nf++)
#pragma unroll
            for (int i = 0; i < 4; i++) acc[mf][nf][i] = 0.f;

    auto issue = [&](int k0, int buf) {
        unsigned* B = sm + buf * PBUF;
#pragma unroll
        for (int it = 0; it < 8; it++) {
            int c = tid + it * 256;
            int panel = c >> 10;
            int cc = c & 1023;
            int row = cc >> 3, ch = cc & 7;
            unsigned* dsm = B + panel * 128 * PS + row * PS + ch * 4;
            const __half* src = (panel == 0)
                ? Xh + (size_t)(m0 + row) * ND + k0 + ch * 8
                : Wt + (size_t)(n0 + row) * ND + k0 + ch * 8;
            cpa16(dsm, src);
        }
    };
    auto compute = [&](unsigned* B) {
#pragma unroll
        for (int kk = 0; kk < 4; kk++) {
            unsigned bh[2][4];
#pragma unroll
            for (int p = 0; p < 2; p++)
                ldsm4(bh[p], B + PWT_ + (warp_n + p * 16) * PS + boff + kk * 8);
#pragma unroll
            for (int mf = 0; mf < 4; mf++) {
                unsigned ah[4];
                ldsm4(ah, B + PXH_ + (warp_m + mf * 16) * PS + aoff + kk * 8);
#pragma unroll
                for (int p = 0; p < 2; p++) {
                    mma_f16(acc[mf][2 * p], ah, &bh[p][0]);
                    mma_f16(acc[mf][2 * p + 1], ah, &bh[p][2]);
                }
            }
        }
    };

    issue(0, 0); CPA_COMMIT();

    const int NT = ND / 64;
    for (int t = 0; t < NT; t++) {
        CPA_WAIT(0);
        __syncthreads();
        if (t + 1 < NT) { issue((t + 1) * 64, (t + 1) & 1); CPA_COMMIT(); }
        compute(sm + (t & 1) * PBUF);
    }

#pragma unroll
    for (int nf = 0; nf < 4; nf++) {
        int n = n0 + warp_n + nf * 8 + l4 * 2;
        int h = n >> 6, hd = n & 63;
        float2 bb = *(const float2*)(bias + n);
#pragma unroll
        for (int mf = 0; mf < 4; mf++) {
            int m = m0 + warp_m + mf * 16 + g4;
            {
                int bbt = m >> 11, s = m & (NS - 1);
                *(unsigned*)(dst + ((size_t)(bbt * NH + h) * NS + s) * HD + hd) =
                    pack2h((acc[mf][nf][0] + bb.x) * sc, (acc[mf][nf][1] + bb.y) * sc);
            }
            {
                int m2 = m + 8;
                int bbt = m2 >> 11, s = m2 & (NS - 1);
                *(unsigned*)(dst + ((size_t)(bbt * NH + h) * NS + s) * HD + hd) =
                    pack2h((acc[mf][nf][2] + bb.x) * sc, (acc[mf][nf][3] + bb.y) * sc);
            }
        }
    }
}

// ---------------------------------------------------------------------------
// Flash attention, warp m-tile = 32, 4 CTAs/SM (single wave: 592 slots >= 512
// CTAs; the 1.15-wave tail at 3 CTAs/SM was the R15 limiter).  2-stage KV ring
// with exactly ONE cp.async group in flight (issue targets (kt+1)&1 while
// computing kt&1 -> disjoint).  GEMM2 loads V frags in half-chunks to keep
// peak regs ~122 (<128 = 65536/(4*128)).  fp16 S accum; p = 2^s f16x2.
// ---------------------------------------------------------------------------
#define AS 36
#define AQ_ 0
#define ABUF0 (128 * AS)
#define KOFF_(b) (ABUF0 + (b) * (128 * AS))
#define VOFF_(b) (KOFF_(b) + 64 * AS)
#define ATT_SMEM ((ABUF0 + 2 * 128 * AS) * 4)   // 55296 B -> 4 CTAs/SM = 221 KB

__global__ __launch_bounds__(128, 4)
void attn_kernel(float* __restrict__ out) {
    extern __shared__ unsigned sm[];
    const int tid = threadIdx.x;
    const int lane = tid & 31, wid = tid >> 5;   // wid 0..3
    const int g4 = lane >> 2, l4 = lane & 3;
    const int qt = blockIdx.x;
    const int bh = blockIdx.y;
    const int aoffL = AOFFS(lane, AS);
    const int boff = BOFFS(lane, AS);
    const int toff = AOFFS(lane, AS);

    const __half* Qg = g_q + (size_t)bh * NS * HD + (size_t)qt * 128 * HD;
    const __half* Kg = g_k + (size_t)bh * NS * HD;
    const __half* Vg = g_v + (size_t)bh * NS * HD;

    auto issueKV = [&](int kt, int buf) {
#pragma unroll
        for (int it = 0; it < 8; it++) {
            int c = tid + it * 128;
            int row = (c >> 3) & 63, ch = c & 7;
            if (c < 512)
                cpa16(sm + KOFF_(buf) + row * AS + ch * 4,
                      Kg + ((size_t)kt * 64 + row) * HD + ch * 8);
            else
                cpa16(sm + VOFF_(buf) + row * AS + ch * 4,
                      Vg + ((size_t)kt * 64 + row) * HD + ch * 8);
        }
    };

    // prologue: Q panel + KV tile 0 as one group (single group in flight)
#pragma unroll
    for (int it = 0; it < 8; it++) {
        int c = tid + it * 128;
        int row = c >> 3, ch = c & 7;
        cpa16(sm + AQ_ + row * AS + ch * 4, Qg + (size_t)row * HD + ch * 8);
    }
    issueKV(0, 0);
    CPA_COMMIT();

    float o[2][8][4];
#pragma unroll
    for (int mb = 0; mb < 2; mb++)
#pragma unroll
        for (int nf = 0; nf < 8; nf++)
#pragma unroll
            for (int i = 0; i < 4; i++) o[mb][nf][i] = 0.f;
    float lsum[2][2] = {{0.f, 0.f}, {0.f, 0.f}};

    const int NT = NS / 64;
    for (int kt = 0; kt < NT; kt++) {
        CPA_WAIT(0);          // sole outstanding group (tile kt) complete
        __syncthreads();      // visible to all; prev compute buffer free
        if (kt + 1 < NT) { issueKV(kt + 1, (kt + 1) & 1); CPA_COMMIT(); }

        unsigned* KB = sm + KOFF_(kt & 1);
        unsigned* VB = sm + VOFF_(kt & 1);

        // GEMM1: S[32 x 64] per warp, fp16 accumulators
        unsigned sd[2][8][2];
#pragma unroll
        for (int mb = 0; mb < 2; mb++)
#pragma unroll
            for (int nf = 0; nf < 8; nf++) {
                sd[mb][nf][0] = 0u;
                sd[mb][nf][1] = 0u;
            }
#pragma unroll
        for (int kk = 0; kk < 4; kk++) {
            unsigned q0[4], q1[4];
            ldsm4(q0, sm + AQ_ + (wid * 32) * AS + aoffL + kk * 8);
            ldsm4(q1, sm + AQ_ + (wid * 32 + 16) * AS + aoffL + kk * 8);
#pragma unroll
            for (int p = 0; p < 4; p++) {
                unsigned bf[4];
                ldsm4(bf, KB + p * 16 * AS + boff + kk * 8);
                mma_f16h(sd[0][2 * p], q0, &bf[0]);
                mma_f16h(sd[0][2 * p + 1], q0, &bf[2]);
                mma_f16h(sd[1][2 * p], q1, &bf[0]);
                mma_f16h(sd[1][2 * p + 1], q1, &bf[2]);
            }
        }

        // GEMM2 per chunk: ap for both m-blocks first, then V frags in two
        // half-loads (bf live = 8 regs, peak regs ~122)
#pragma unroll
        for (int kk = 0; kk < 4; kk++) {
            unsigned ap[2][4];
#pragma unroll
            for (int mb = 0; mb < 2; mb++) {
                ap[mb][0] = hex2(sd[mb][2 * kk][0]);
                ap[mb][1] = hex2(sd[mb][2 * kk][1]);
                ap[mb][2] = hex2(sd[mb][2 * kk + 1][0]);
                ap[mb][3] = hex2(sd[mb][2 * kk + 1][1]);
                __half2 h0 = __hadd2(u2h2(ap[mb][0]), u2h2(ap[mb][2]));
                __half2 h1 = __hadd2(u2h2(ap[mb][1]), u2h2(ap[mb][3]));
                float2 f0 = __half22float2(h0);
                float2 f1 = __half22float2(h1);
                lsum[mb][0] += f0.x + f0.y;
                lsum[mb][1] += f1.x + f1.y;
            }
#pragma unroll
            for (int ph = 0; ph < 2; ph++) {
                unsigned bfA[4], bfB[4];
                ldsm4t(bfA, VB + kk * 16 * AS + toff + (2 * ph) * 8);
                ldsm4t(bfB, VB + kk * 16 * AS + toff + (2 * ph + 1) * 8);
#pragma unroll
                for (int mb = 0; mb < 2; mb++) {
                    mma_f16(o[mb][4 * ph],     ap[mb], &bfA[0]);
                    mma_f16(o[mb][4 * ph + 1], ap[mb], &bfA[2]);
                    mma_f16(o[mb][4 * ph + 2], ap[mb], &bfB[0]);
                    mma_f16(o[mb][4 * ph + 3], ap[mb], &bfB[2]);
                }
            }
        }
    }

    const int b = bh >> 4, h = bh & 15;
#pragma unroll
    for (int mb = 0; mb < 2; mb++) {
        float l0 = lsum[mb][0], l1 = lsum[mb][1];
        l0 += __shfl_xor_sync(0xffffffffu, l0, 1);
        l0 += __shfl_xor_sync(0xffffffffu, l0, 2);
        l1 += __shfl_xor_sync(0xffffffffu, l1, 1);
        l1 += __shfl_xor_sync(0xffffffffu, l1, 2);
        const float inv0 = 1.0f / l0, inv1 = 1.0f / l1;

        const int r0 = qt * 128 + wid * 32 + mb * 16 + g4;
        float* orow0 = out + (size_t)(b * NS + r0) * ND + h * HD;
        float* orow1 = out + (size_t)(b * NS + r0 + 8) * ND + h * HD;
#pragma unroll
        for (int nf = 0; nf < 8; nf++) {
            int col = nf * 8 + l4 * 2;
            float2 v0 = {o[mb][nf][0] * inv0, o[mb][nf][1] * inv0};
            float2 v1 = {o[mb][nf][2] * inv1, o[mb][nf][3] * inv1};
            *(float2*)(orow0 + col) = v0;
            *(float2*)(orow1 + col) = v1;
        }
    }
}

// ---------------------------------------------------------------------------
extern "C" void kernel_launch(void* const* d_in, const int* in_sizes, int n_in,
                              void* d_out, int out_size) {
    const float* query = (const float*)d_in[0];
    const float* key_  = (const float*)d_in[1];
    const float* value = (const float*)d_in[2];
    const float* Wq    = (const float*)d_in[3];
    const float* bq    = (const float*)d_in[4];
    const float* Wk    = (const float*)d_in[5];
    const float* bk    = (const float*)d_in[6];
    const float* Wv    = (const float*)d_in[7];
    const float* bv    = (const float*)d_in[8];
    float* out = (float*)d_out;

    cudaFuncSetAttribute(proj_kernel, cudaFuncAttributeMaxDynamicSharedMemorySize,
                         PROJ_SMEM);
    cudaFuncSetAttribute(attn_kernel, cudaFuncAttributeMaxDynamicSharedMemorySize,
                         ATT_SMEM);

    dim3 cxg(NM * ND / 4 / 256, 3);
    convx_kernel<<<cxg, 256>>>(query, key_, value);
    dim3 cwg(ND / 32, ND / 32, 3);
    convw_kernel<<<cwg, dim3(32, 8)>>>(Wq, Wk, Wv);

    dim3 pg(ND / 128, NM / 128, 3);
    proj_kernel<<<pg, 256, PROJ_SMEM>>>(bq, bk, bv);

    dim3 ag(NS / 128, NB * NH);
    attn_kernel<<<ag, 128, ATT_SMEM>>>(out);
}

// round 17
// speedup vs baseline: 1.0253x; 1.0253x over previous
#include <cuda_runtime.h>
#include <cuda_fp16.h>

#define NB 2
#define NS 2048
#define ND 1024
#define NH 16
#define HD 64
#define NM (NB * NS)

// fp16 intermediates
__device__ __half g_q[NB * NH * NS * HD];
__device__ __half g_k[NB * NH * NS * HD];
__device__ __half g_v[NB * NH * NS * HD];
__device__ __half g_xh[3 * NM * ND];   // X fp16 (natural [m][k])
__device__ __half g_wt[3 * ND * ND];   // W fp16, NATURAL K-major [k][n] (no transpose)

// ---------------------------------------------------------------------------
// primitives
// ---------------------------------------------------------------------------
static __device__ __forceinline__ void mma_f16(float* d, const unsigned* a,
                                               const unsigned* b) {
    asm volatile(
        "mma.sync.aligned.m16n8k16.row.col.f32.f16.f16.f32 "
        "{%0,%1,%2,%3}, {%4,%5,%6,%7}, {%8,%9}, {%0,%1,%2,%3};"
        : "+f"(d[0]), "+f"(d[1]), "+f"(d[2]), "+f"(d[3])
        : "r"(a[0]), "r"(a[1]), "r"(a[2]), "r"(a[3]), "r"(b[0]), "r"(b[1]));
}
static __device__ __forceinline__ void mma_f16h(unsigned* d, const unsigned* a,
                                                const unsigned* b) {
    asm volatile(
        "mma.sync.aligned.m16n8k16.row.col.f16.f16.f16.f16 "
        "{%0,%1}, {%2,%3,%4,%5}, {%6,%7}, {%0,%1};"
        : "+r"(d[0]), "+r"(d[1])
        : "r"(a[0]), "r"(a[1]), "r"(a[2]), "r"(a[3]), "r"(b[0]), "r"(b[1]));
}
static __device__ __forceinline__ void ldsm4(unsigned* r, const unsigned* p) {
    unsigned a = (unsigned)__cvta_generic_to_shared(p);
    asm volatile("ldmatrix.sync.aligned.m8n8.x4.shared.b16 {%0,%1,%2,%3}, [%4];"
                 : "=r"(r[0]), "=r"(r[1]), "=r"(r[2]), "=r"(r[3]) : "r"(a));
}
static __device__ __forceinline__ void ldsm4t(unsigned* r, const unsigned* p) {
    unsigned a = (unsigned)__cvta_generic_to_shared(p);
    asm volatile("ldmatrix.sync.aligned.m8n8.x4.trans.shared.b16 {%0,%1,%2,%3}, [%4];"
                 : "=r"(r[0]), "=r"(r[1]), "=r"(r[2]), "=r"(r[3]) : "r"(a));
}
static __device__ __forceinline__ void cpa16(const unsigned* smdst, const void* gsrc) {
    unsigned a = (unsigned)__cvta_generic_to_shared(smdst);
    asm volatile("cp.async.cg.shared.global [%0], [%1], 16;" :: "r"(a), "l"(gsrc));
}
#define CPA_COMMIT() asm volatile("cp.async.commit_group;" ::: "memory")
#define CPA_WAIT(n)  asm volatile("cp.async.wait_group %0;" :: "n"(n) : "memory")

static __device__ __forceinline__ unsigned pack2h(float x, float y) {
    __half2 h = __floats2half2_rn(x, y);
    return *(unsigned*)&h;
}
static __device__ __forceinline__ unsigned hex2(unsigned x) {
    unsigned y;
    asm("ex2.approx.f16x2 %0, %1;" : "=r"(y) : "r"(x));
    return y;
}
static __device__ __forceinline__ __half2 u2h2(unsigned x) {
    return *(__half2*)&x;
}

// fragment lane->word offsets (row stride S words)
#define AOFFS(lane, S) \
    ((((lane) & 7) + ((((lane) >> 3) & 1) << 3)) * (S) + ((((lane) >> 4) & 1) << 2))
#define BOFFS(lane, S) \
    ((((lane) & 7) + ((((lane) >> 4) & 1) << 3)) * (S) + ((((lane) >> 3) & 1) << 2))

// ---------------------------------------------------------------------------
// Convert X -> fp16 (elementwise)
// ---------------------------------------------------------------------------
__global__ void convx_kernel(const float* __restrict__ xq,
                             const float* __restrict__ xk,
                             const float* __restrict__ xv) {
    const int z = blockIdx.y;
    const float* X = (z == 0) ? xq : (z == 1) ? xk : xv;
    unsigned* xh = (unsigned*)(g_xh + (size_t)z * NM * ND);
    int i = blockIdx.x * blockDim.x + threadIdx.x;
    float4 v = ((const float4*)X)[i];
    xh[2 * i]     = pack2h(v.x, v.y);
    xh[2 * i + 1] = pack2h(v.z, v.w);
}

// ---------------------------------------------------------------------------
// Convert W -> fp16, NATURAL layout (no transpose; proj uses ldmatrix.trans)
// ---------------------------------------------------------------------------
__global__ void convw_kernel(const float* __restrict__ wq,
                             const float* __restrict__ wk,
                             const float* __restrict__ wv) {
    const int z = blockIdx.y;
    const float* W = (z == 0) ? wq : (z == 1) ? wk : wv;
    unsigned* wh = (unsigned*)(g_wt + (size_t)z * ND * ND);
    int i = blockIdx.x * blockDim.x + threadIdx.x;
    float4 v = ((const float4*)W)[i];
    wh[2 * i]     = pack2h(v.x, v.y);
    wh[2 * i + 1] = pack2h(v.z, v.w);
}

// ---------------------------------------------------------------------------
// Projection GEMM: single-term fp16, BK=64, 2-stage (1 group in flight).
// W kept K-major [k][n]; B fragments via ldmatrix.trans (same as V in attn).
// X panel: 128 rows x 36-word stride.  W panel: 64 k-rows x 68-word stride
// (68 mod 32 = 4 -> ldsm phases conflict-free, same class as 36).
// ---------------------------------------------------------------------------
#define PS 36
#define WS 68
#define PBUF (128 * PS + 64 * WS)         // 8960 words per stage
#define PXH_ 0
#define PWT_ (128 * PS)
#define PROJ_SMEM (2 * PBUF * 4)          // 71680 B -> 2 CTAs/SM

__global__ __launch_bounds__(256, 2)
void proj_kernel(const float* __restrict__ bq, const float* __restrict__ bk,
                 const float* __restrict__ bv) {
    extern __shared__ unsigned sm[];
    const int z = blockIdx.z;
    const float* bias = (z == 0) ? bq : (z == 1) ? bk : bv;
    __half* dst = (z == 0) ? g_q : (z == 1) ? g_k : g_v;
    const float sc = (z == 0) ? 0.125f : (z == 1) ? 1.4426950408889634f : 1.0f;
    const __half* Xh = g_xh + (size_t)z * NM * ND;
    const __half* Wg = g_wt + (size_t)z * ND * ND;

    const int tid = threadIdx.x;
    const int lane = tid & 31, wid = tid >> 5;
    const int warp_m = (wid >> 2) * 64, warp_n = (wid & 3) * 32;
    const int m0 = blockIdx.y * 128, n0 = blockIdx.x * 128;
    const int g4 = lane >> 2, l4 = lane & 3;
    const int aoff = AOFFS(lane, PS);
    const int woff = AOFFS(lane, WS);     // trans-B lane offset (rows = k)

    float acc[4][4][4];
#pragma unroll
    for (int mf = 0; mf < 4; mf++)
#pragma unroll
        for (int nf = 0; nf < 4; nf++)
#pragma unroll
            for (int i = 0; i < 4; i++) acc[mf][nf][i] = 0.f;

    // one BK=64 stage: X 128 rows x 8 chunks + W 64 rows x 16 chunks = 2048
    auto issue = [&](int k0, int buf) {
        unsigned* B = sm + buf * PBUF;
#pragma unroll
        for (int it = 0; it < 8; it++) {
            int c = tid + it * 256;
            if (c < 1024) {
                int row = c >> 3, ch = c & 7;
                cpa16(B + PXH_ + row * PS + ch * 4,
                      Xh + (size_t)(m0 + row) * ND + k0 + ch * 8);
            } else {
                int cc = c - 1024;
                int row = cc >> 4, ch = cc & 15;   // k-row 0..63, 16 chunks of 16B
                cpa16(B + PWT_ + row * WS + ch * 4,
                      Wg + (size_t)(k0 + row) * ND + n0 + ch * 8);
            }
        }
    };
    auto compute = [&](unsigned* B) {
#pragma unroll
        for (int kk = 0; kk < 4; kk++) {
            unsigned bh[2][4];
#pragma unroll
            for (int p = 0; p < 2; p++)
                ldsm4t(bh[p], B + PWT_ + kk * 16 * WS + woff + (warp_n >> 1) + p * 8);
#pragma unroll
            for (int mf = 0; mf < 4; mf++) {
                unsigned ah[4];
                ldsm4(ah, B + PXH_ + (warp_m + mf * 16) * PS + aoff + kk * 8);
#pragma unroll
                for (int p = 0; p < 2; p++) {
                    mma_f16(acc[mf][2 * p], ah, &bh[p][0]);
                    mma_f16(acc[mf][2 * p + 1], ah, &bh[p][2]);
                }
            }
        }
    };

    issue(0, 0); CPA_COMMIT();

    const int NT = ND / 64;
    for (int t = 0; t < NT; t++) {
        CPA_WAIT(0);
        __syncthreads();
        if (t + 1 < NT) { issue((t + 1) * 64, (t + 1) & 1); CPA_COMMIT(); }
        compute(sm + (t & 1) * PBUF);
    }

    // epilogue: bias, scale, fp16 head-layout store
#pragma unroll
    for (int nf = 0; nf < 4; nf++) {
        int n = n0 + warp_n + nf * 8 + l4 * 2;
        int h = n >> 6, hd = n & 63;
        float2 bb = *(const float2*)(bias + n);
#pragma unroll
        for (int mf = 0; mf < 4; mf++) {
            int m = m0 + warp_m + mf * 16 + g4;
            {
                int bbt = m >> 11, s = m & (NS - 1);
                *(unsigned*)(dst + ((size_t)(bbt * NH + h) * NS + s) * HD + hd) =
                    pack2h((acc[mf][nf][0] + bb.x) * sc, (acc[mf][nf][1] + bb.y) * sc);
            }
            {
                int m2 = m + 8;
                int bbt = m2 >> 11, s = m2 & (NS - 1);
                *(unsigned*)(dst + ((size_t)(bbt * NH + h) * NS + s) * HD + hd) =
                    pack2h((acc[mf][nf][2] + bb.x) * sc, (acc[mf][nf][3] + bb.y) * sc);
            }
        }
    }
}

// ---------------------------------------------------------------------------
// Flash attention (reverted to the R15 best: warp m-tile = 32, 3 CTAs/SM,
// 3-stage KV ring, fp16 S accumulators, p = 2^s via ex2.f16x2).
// ---------------------------------------------------------------------------
#define AS 36
#define AQ_ 0
#define ABUF0 (128 * AS)
#define KOFF_(b) (ABUF0 + (b) * (128 * AS))
#define VOFF_(b) (KOFF_(b) + 64 * AS)
#define ATT_SMEM ((ABUF0 + 3 * 128 * AS) * 4)   // 73728 B -> 3 CTAs/SM

__global__ __launch_bounds__(128, 3)
void attn_kernel(float* __restrict__ out) {
    extern __shared__ unsigned sm[];
    const int tid = threadIdx.x;
    const int lane = tid & 31, wid = tid >> 5;
    const int g4 = lane >> 2, l4 = lane & 3;
    const int qt = blockIdx.x;
    const int bh = blockIdx.y;
    const int aoffL = AOFFS(lane, AS);
    const int boff = BOFFS(lane, AS);
    const int toff = AOFFS(lane, AS);

    const __half* Qg = g_q + (size_t)bh * NS * HD + (size_t)qt * 128 * HD;
    const __half* Kg = g_k + (size_t)bh * NS * HD;
    const __half* Vg = g_v + (size_t)bh * NS * HD;

    auto issueKV = [&](int kt, int buf) {
#pragma unroll
        for (int it = 0; it < 8; it++) {
            int c = tid + it * 128;
            int row = (c >> 3) & 63, ch = c & 7;
            if (c < 512)
                cpa16(sm + KOFF_(buf) + row * AS + ch * 4,
                      Kg + ((size_t)kt * 64 + row) * HD + ch * 8);
            else
                cpa16(sm + VOFF_(buf) + row * AS + ch * 4,
                      Vg + ((size_t)kt * 64 + row) * HD + ch * 8);
        }
    };

#pragma unroll
    for (int it = 0; it < 8; it++) {
        int c = tid + it * 128;
        int row = c >> 3, ch = c & 7;
        cpa16(sm + AQ_ + row * AS + ch * 4, Qg + (size_t)row * HD + ch * 8);
    }
    issueKV(0, 0);
    CPA_COMMIT();
    issueKV(1, 1);
    CPA_COMMIT();

    float o[2][8][4];
#pragma unroll
    for (int mb = 0; mb < 2; mb++)
#pragma unroll
        for (int nf = 0; nf < 8; nf++)
#pragma unroll
            for (int i = 0; i < 4; i++) o[mb][nf][i] = 0.f;
    float lsum[2][2] = {{0.f, 0.f}, {0.f, 0.f}};

    const int NT = NS / 64;
    for (int kt = 0; kt < NT; kt++) {
        if (kt == NT - 1) CPA_WAIT(0); else CPA_WAIT(1);
        __syncthreads();
        if (kt + 2 < NT) { issueKV(kt + 2, (kt + 2) % 3); CPA_COMMIT(); }

        unsigned* KB = sm + KOFF_(kt % 3);
        unsigned* VB = sm + VOFF_(kt % 3);

        unsigned sd[2][8][2];
#pragma unroll
        for (int mb = 0; mb < 2; mb++)
#pragma unroll
            for (int nf = 0; nf < 8; nf++) {
                sd[mb][nf][0] = 0u;
                sd[mb][nf][1] = 0u;
            }
#pragma unroll
        for (int kk = 0; kk < 4; kk++) {
            unsigned q0[4], q1[4];
            ldsm4(q0, sm + AQ_ + (wid * 32) * AS + aoffL + kk * 8);
            ldsm4(q1, sm + AQ_ + (wid * 32 + 16) * AS + aoffL + kk * 8);
#pragma unroll
            for (int p = 0; p < 4; p++) {
                unsigned bf[4];
                ldsm4(bf, KB + p * 16 * AS + boff + kk * 8);
                mma_f16h(sd[0][2 * p], q0, &bf[0]);
                mma_f16h(sd[0][2 * p + 1], q0, &bf[2]);
                mma_f16h(sd[1][2 * p], q1, &bf[0]);
                mma_f16h(sd[1][2 * p + 1], q1, &bf[2]);
            }
        }

        __half2 hs[2][2];
#pragma unroll
        for (int mb = 0; mb < 2; mb++) {
            hs[mb][0] = __floats2half2_rn(0.f, 0.f);
            hs[mb][1] = __floats2half2_rn(0.f, 0.f);
        }
#pragma unroll
        for (int kk = 0; kk < 4; kk++) {
            unsigned bf[4][4];
#pragma unroll
            for (int p = 0; p < 4; p++)
                ldsm4t(bf[p], VB + kk * 16 * AS + toff + p * 8);
#pragma unroll
            for (int mb = 0; mb < 2; mb++) {
                unsigned ap[4];
                ap[0] = hex2(sd[mb][2 * kk][0]);
                ap[1] = hex2(sd[mb][2 * kk][1]);
                ap[2] = hex2(sd[mb][2 * kk + 1][0]);
                ap[3] = hex2(sd[mb][2 * kk + 1][1]);
                hs[mb][0] = __hadd2(hs[mb][0], __hadd2(u2h2(ap[0]), u2h2(ap[2])));
                hs[mb][1] = __hadd2(hs[mb][1], __hadd2(u2h2(ap[1]), u2h2(ap[3])));
#pragma unroll
                for (int p = 0; p < 4; p++) {
                    mma_f16(o[mb][2 * p], ap, &bf[p][0]);
                    mma_f16(o[mb][2 * p + 1], ap, &bf[p][2]);
                }
            }
        }
#pragma unroll
        for (int mb = 0; mb < 2; mb++) {
            float2 f0 = __half22float2(hs[mb][0]);
            float2 f1 = __half22float2(hs[mb][1]);
            lsum[mb][0] += f0.x + f0.y;
            lsum[mb][1] += f1.x + f1.y;
        }
    }

    const int b = bh >> 4, h = bh & 15;
#pragma unroll
    for (int mb = 0; mb < 2; mb++) {
        float l0 = lsum[mb][0], l1 = lsum[mb][1];
        l0 += __shfl_xor_sync(0xffffffffu, l0, 1);
        l0 += __shfl_xor_sync(0xffffffffu, l0, 2);
        l1 += __shfl_xor_sync(0xffffffffu, l1, 1);
        l1 += __shfl_xor_sync(0xffffffffu, l1, 2);
        const float inv0 = 1.0f / l0, inv1 = 1.0f / l1;

        const int r0 = qt * 128 + wid * 32 + mb * 16 + g4;
        float* orow0 = out + (size_t)(b * NS + r0) * ND + h * HD;
        float* orow1 = out + (size_t)(b * NS + r0 + 8) * ND + h * HD;
#pragma unroll
        for (int nf = 0; nf < 8; nf++) {
            int col = nf * 8 + l4 * 2;
            float2 v0 = {o[mb][nf][0] * inv0, o[mb][nf][1] * inv0};
            float2 v1 = {o[mb][nf][2] * inv1, o[mb][nf][3] * inv1};
            *(float2*)(orow0 + col) = v0;
            *(float2*)(orow1 + col) = v1;
        }
    }
}

// ---------------------------------------------------------------------------
extern "C" void kernel_launch(void* const* d_in, const int* in_sizes, int n_in,
                              void* d_out, int out_size) {
    const float* query = (const float*)d_in[0];
    const float* key_  = (const float*)d_in[1];
    const float* value = (const float*)d_in[2];
    const float* Wq    = (const float*)d_in[3];
    const float* bq    = (const float*)d_in[4];
    const float* Wk    = (const float*)d_in[5];
    const float* bk    = (const float*)d_in[6];
    const float* Wv    = (const float*)d_in[7];
    const float* bv    = (const float*)d_in[8];
    float* out = (float*)d_out;

    cudaFuncSetAttribute(proj_kernel, cudaFuncAttributeMaxDynamicSharedMemorySize,
                         PROJ_SMEM);
    cudaFuncSetAttribute(attn_kernel, cudaFuncAttributeMaxDynamicSharedMemorySize,
                         ATT_SMEM);

    dim3 cxg(NM * ND / 4 / 256, 3);
    convx_kernel<<<cxg, 256>>>(query, key_, value);
    dim3 cwg(ND * ND / 4 / 256, 3);
    convw_kernel<<<cwg, 256>>>(Wq, Wk, Wv);

    dim3 pg(ND / 128, NM / 128, 3);
    proj_kernel<<<pg, 256, PROJ_SMEM>>>(bq, bk, bv);

    dim3 ag(NS / 128, NB * NH);
    attn_kernel<<<ag, 128, ATT_SMEM>>>(out);
}